// round 12
// baseline (speedup 1.0000x reference)
#include <cuda_runtime.h>
#include <cuda_bf16.h>
#include <cuda_fp16.h>
#include <cstdint>

#define NN 100000
#define RR 8
#define EE 800000
#define DD 128
#define BB 4
#define RN (RR*NN)        // 800000
#define RE (RR*EE)        // 6400000
#define SCAN_BLOCKS ((RN + 1023) / 1024)   // 782

// ---------------- device scratch (static, no allocation) ----------------
__device__ int    g_is64;
__device__ int    g_deg[RN];
__device__ int    g_scan[RN];
__device__ int    g_bsum[1024];
__device__ int    g_bsumx[1024];
__device__ int    g_rowstart[RN];
__device__ int    g_cursor[RN];
__device__ float  g_invdeg[RN];
__device__ int    g_csr[RE];
__device__ __half g_xh[(size_t)NN * DD];    // packed fp16 copy of x (25.6 MB)
__device__ __half g_Yh[(size_t)NN * 512];   // fp16 basis-combined messages (102.4 MB)
__device__ float  g_h1[(size_t)NN * DD];
__device__ float  g_h2[(size_t)NN * DD];

// ---------------- edge index helpers ----------------
// int64 edge values are < 2^31, little-endian: low 32-bit word == value.
__device__ __forceinline__ int edge_at(const void* p, int i, int is64) {
    if (is64) return ((const int*)p)[2 * i];
    return ((const int*)p)[i];
}

__global__ void k_detect(const void* srcp, const void* dstp) {
    if (threadIdx.x == 0 && blockIdx.x == 0) {
        const long long* s = (const long long*)srcp;
        const long long* d = (const long long*)dstp;
        int ok = 1;
        for (int i = 0; i < 64; i++) {
            long long a = s[i], b = d[i];
            if (a < 0 || a >= NN || b < 0 || b >= NN) { ok = 0; break; }
        }
        g_is64 = ok;
    }
}

__global__ void k_zero() {
    int i = blockIdx.x * blockDim.x + threadIdx.x;
    if (i < RN) { g_deg[i] = 0; g_cursor[i] = 0; }
}

// pack x to fp16
__global__ void k_x2h(const float* __restrict__ x) {
    int i = blockIdx.x * blockDim.x + threadIdx.x;   // one float4 -> half4
    if (i >= NN * DD / 4) return;
    float4 v = *(const float4*)&x[(size_t)i * 4];
    __half2 h0 = __floats2half2_rn(v.x, v.y);
    __half2 h1 = __floats2half2_rn(v.z, v.w);
    uint2 o;
    o.x = *(uint32_t*)&h0;
    o.y = *(uint32_t*)&h1;
    *(uint2*)&g_xh[(size_t)i * 4] = o;
}

__global__ void k_degree(const void* dstp) {
    int i = blockIdx.x * blockDim.x + threadIdx.x;
    if (i >= RE) return;
    int is64 = g_is64;
    int d = edge_at(dstp, i, is64);
    int r = i / EE;
    atomicAdd(&g_deg[r * NN + d], 1);
}

__global__ void k_scan1() {
    __shared__ int sh[1024];
    int gid = blockIdx.x * 1024 + threadIdx.x;
    int v = (gid < RN) ? g_deg[gid] : 0;
    sh[threadIdx.x] = v;
    __syncthreads();
    for (int off = 1; off < 1024; off <<= 1) {
        int t = (threadIdx.x >= off) ? sh[threadIdx.x - off] : 0;
        __syncthreads();
        sh[threadIdx.x] += t;
        __syncthreads();
    }
    if (gid < RN) g_scan[gid] = sh[threadIdx.x];
    if (threadIdx.x == 1023) g_bsum[blockIdx.x] = sh[1023];
}

__global__ void k_scan2(int nb) {
    __shared__ int sh[1024];
    int v = (threadIdx.x < nb) ? g_bsum[threadIdx.x] : 0;
    sh[threadIdx.x] = v;
    __syncthreads();
    for (int off = 1; off < 1024; off <<= 1) {
        int t = (threadIdx.x >= off) ? sh[threadIdx.x - off] : 0;
        __syncthreads();
        sh[threadIdx.x] += t;
        __syncthreads();
    }
    if (threadIdx.x < nb) g_bsumx[threadIdx.x] = sh[threadIdx.x] - v;
}

__global__ void k_scan3() {
    int gid = blockIdx.x * blockDim.x + threadIdx.x;
    if (gid >= RN) return;
    int deg = g_deg[gid];
    g_rowstart[gid] = g_scan[gid] - deg + g_bsumx[gid / 1024];
    g_invdeg[gid] = 1.0f / (float)max(deg, 1);
}

__global__ void k_fill(const void* srcp, const void* dstp) {
    int i = blockIdx.x * blockDim.x + threadIdx.x;
    if (i >= RE) return;
    int is64 = g_is64;
    int s = edge_at(srcp, i, is64);
    int d = edge_at(dstp, i, is64);
    int r = i / EE;
    int row = r * NN + d;
    int pos = g_rowstart[row] + atomicAdd(&g_cursor[row], 1);
    g_csr[pos] = s;
}

// One warp per destination node; gathers fp16 x rows, accumulates fp32,
// folds w_comp[r][b] * invdeg, writes Y[n, 0:512] in fp16.
__global__ void k_gather(const float* __restrict__ wcomp) {
    __shared__ float swc[RR * BB];
    if (threadIdx.x < RR * BB) swc[threadIdx.x] = wcomp[threadIdx.x];
    __syncthreads();
    int warp = threadIdx.x >> 5;
    int lane = threadIdx.x & 31;
    int n = blockIdx.x * 8 + warp;
    if (n >= NN) return;

    float4 acc[BB];
    #pragma unroll
    for (int b = 0; b < BB; b++) acc[b] = make_float4(0.f, 0.f, 0.f, 0.f);

    #pragma unroll
    for (int r = 0; r < RR; r++) {
        int row = r * NN + n;
        int st = g_rowstart[row];
        int len = g_deg[row];
        float t0 = 0.f, t1 = 0.f, t2 = 0.f, t3 = 0.f;
        if (len > 0) {
            int s = g_csr[st];
            for (int j = 0; j < len - 1; j++) {
                int sn = g_csr[st + j + 1];
                uint2 hv = *(const uint2*)&g_xh[(size_t)s * DD + lane * 4];
                float2 f0 = __half22float2(*(__half2*)&hv.x);
                float2 f1 = __half22float2(*(__half2*)&hv.y);
                t0 += f0.x; t1 += f0.y; t2 += f1.x; t3 += f1.y;
                s = sn;
            }
            uint2 hv = *(const uint2*)&g_xh[(size_t)s * DD + lane * 4];
            float2 f0 = __half22float2(*(__half2*)&hv.x);
            float2 f1 = __half22float2(*(__half2*)&hv.y);
            t0 += f0.x; t1 += f0.y; t2 += f1.x; t3 += f1.y;
        }
        float iv = g_invdeg[row];
        #pragma unroll
        for (int b = 0; b < BB; b++) {
            float c = swc[r * BB + b] * iv;
            acc[b].x += c * t0; acc[b].y += c * t1;
            acc[b].z += c * t2; acc[b].w += c * t3;
        }
    }
    #pragma unroll
    for (int b = 0; b < BB; b++) {
        __half2 h0 = __floats2half2_rn(acc[b].x, acc[b].y);
        __half2 h1 = __floats2half2_rn(acc[b].z, acc[b].w);
        uint2 o;
        o.x = *(uint32_t*)&h0;
        o.y = *(uint32_t*)&h1;
        *(uint2*)&g_Yh[(size_t)n * 512 + b * DD + lane * 4] = o;
    }
}

// ---------------- fp16 m16n8k16 mma.sync GEMM ----------------
// C[M,128] = A1[M,K1]@B1 (+ A2[M,K2]@B2) (+bias)(relu?)   fp32 accum.
// ahalf: A operands are pre-packed fp16 (read uint2, store raw);
// else fp32 (read float4, convert at staging). B always fp32.
__device__ __forceinline__ uint32_t pack_h2(float a, float b) {
    __half2 h = __floats2half2_rn(a, b);
    return *(uint32_t*)&h;
}
__device__ __forceinline__ void mma_f16(float* d, const uint32_t* a, uint32_t b0, uint32_t b1) {
    asm volatile(
        "mma.sync.aligned.m16n8k16.row.col.f32.f16.f16.f32 "
        "{%0,%1,%2,%3}, {%4,%5,%6,%7}, {%8,%9}, {%0,%1,%2,%3};"
        : "+f"(d[0]), "+f"(d[1]), "+f"(d[2]), "+f"(d[3])
        : "r"(a[0]), "r"(a[1]), "r"(a[2]), "r"(a[3]), "r"(b0), "r"(b1));
}

#define ASTRIDE 20
#define BSTRIDE 132
__global__ void __launch_bounds__(256, 2)
k_gemm(const void* __restrict__ A1, int K1, const float* __restrict__ B1,
       const void* __restrict__ A2, int K2, const float* __restrict__ B2,
       int M, float* __restrict__ Cout,
       const float* __restrict__ bias, int relu, int ahalf) {
    __shared__ uint32_t As2[128][ASTRIDE];   // half2: [row][kp], kp = k/2 (16 valid)
    __shared__ uint32_t Bs2[16][BSTRIDE];    // half2: [kp][n]
    const int t = threadIdx.x;
    const int lane = t & 31, wid = t >> 5;
    const int g = lane >> 2, tg = lane & 3;
    const int wm = wid >> 1, wn = wid & 1;      // 4 x 2 warp grid
    const int r0 = blockIdx.x * 128;

    float acc[2][8][4];
    #pragma unroll
    for (int mi = 0; mi < 2; mi++)
        #pragma unroll
        for (int nj = 0; nj < 8; nj++)
            #pragma unroll
            for (int q = 0; q < 4; q++) acc[mi][nj][q] = 0.f;

    float4 ra[4];      // fp32 A prefetch
    uint2  rah[4];     // fp16 A prefetch
    float4 rb[4];      // B prefetch

    #define LDG_TILE(A, Bm, K, kt) do { \
        if (ahalf) { \
            const __half* Ah = (const __half*)(A); \
            _Pragma("unroll") \
            for (int p = 0; p < 4; p++) { \
                int idx = t + 256 * p; \
                int rowA = idx >> 3, c4 = idx & 7; \
                int gr = r0 + rowA; \
                uint2 v = make_uint2(0u, 0u); \
                if (gr < M) v = *(const uint2*)&Ah[(size_t)gr * (K) + (kt) + c4 * 4]; \
                rah[p] = v; \
            } \
        } else { \
            const float* Af = (const float*)(A); \
            _Pragma("unroll") \
            for (int p = 0; p < 4; p++) { \
                int idx = t + 256 * p; \
                int rowA = idx >> 3, c4 = idx & 7; \
                int gr = r0 + rowA; \
                float4 v = make_float4(0.f, 0.f, 0.f, 0.f); \
                if (gr < M) v = *(const float4*)&Af[(size_t)gr * (K) + (kt) + c4 * 4]; \
                ra[p] = v; \
            } \
        } \
        _Pragma("unroll") \
        for (int p = 0; p < 2; p++) { \
            int u = t + 256 * p; \
            int kp = u >> 5, cB = (u & 31) * 4; \
            rb[2 * p]     = *(const float4*)&(Bm)[(size_t)((kt) + 2 * kp)     * 128 + cB]; \
            rb[2 * p + 1] = *(const float4*)&(Bm)[(size_t)((kt) + 2 * kp + 1) * 128 + cB]; \
        } \
    } while(0)
    #define STS_TILE() do { \
        if (ahalf) { \
            _Pragma("unroll") \
            for (int p = 0; p < 4; p++) { \
                int idx = t + 256 * p; \
                int rowA = idx >> 3, c4 = idx & 7; \
                As2[rowA][c4 * 2 + 0] = rah[p].x; \
                As2[rowA][c4 * 2 + 1] = rah[p].y; \
            } \
        } else { \
            _Pragma("unroll") \
            for (int p = 0; p < 4; p++) { \
                int idx = t + 256 * p; \
                int rowA = idx >> 3, c4 = idx & 7; \
                As2[rowA][c4 * 2 + 0] = pack_h2(ra[p].x, ra[p].y); \
                As2[rowA][c4 * 2 + 1] = pack_h2(ra[p].z, ra[p].w); \
            } \
        } \
        _Pragma("unroll") \
        for (int p = 0; p < 2; p++) { \
            int u = t + 256 * p; \
            int kp = u >> 5, cB = (u & 31) * 4; \
            float4 lo = rb[2 * p], hi = rb[2 * p + 1]; \
            Bs2[kp][cB + 0] = pack_h2(lo.x, hi.x); \
            Bs2[kp][cB + 1] = pack_h2(lo.y, hi.y); \
            Bs2[kp][cB + 2] = pack_h2(lo.z, hi.z); \
            Bs2[kp][cB + 3] = pack_h2(lo.w, hi.w); \
        } \
    } while(0)

    const void*  Aph[2] = { A1, A2 };
    const float* Bph[2] = { B1, B2 };
    const int    Kph[2] = { K1, K2 };

    LDG_TILE(A1, B1, K1, 0);

    #pragma unroll
    for (int ph = 0; ph < 2; ph++) {
        const void* A = Aph[ph];
        const float* Bm = Bph[ph];
        const int K = Kph[ph];
        if (A == nullptr) continue;
        const int nt = K >> 5;
        for (int c = 0; c < nt; c++) {
            STS_TILE();
            __syncthreads();
            if (c + 1 < nt) {
                LDG_TILE(A, Bm, K, (c + 1) * 32);
            } else if (ph == 0 && Aph[1] != nullptr) {
                LDG_TILE(Aph[1], Bph[1], Kph[1], 0);
            }
            // two k16 blocks per 32-K tile
            #pragma unroll
            for (int kc = 0; kc < 2; kc++) {
                int kb = kc * 8;                 // half2 base within tile
                uint32_t af[2][4];
                #pragma unroll
                for (int mi = 0; mi < 2; mi++) {
                    int m = wm * 32 + mi * 16 + g;
                    af[mi][0] = As2[m][kb + tg];
                    af[mi][1] = As2[m + 8][kb + tg];
                    af[mi][2] = As2[m][kb + tg + 4];
                    af[mi][3] = As2[m + 8][kb + tg + 4];
                }
                #pragma unroll
                for (int nj = 0; nj < 8; nj++) {
                    int n = wn * 64 + nj * 8 + g;
                    uint32_t b0 = Bs2[kb + tg][n];
                    uint32_t b1 = Bs2[kb + tg + 4][n];
                    mma_f16(acc[0][nj], af[0], b0, b1);
                    mma_f16(acc[1][nj], af[1], b0, b1);
                }
            }
            __syncthreads();
        }
    }

    // epilogue: thread (g,tg) owns rows m0+g(+8), cols n0+nj*8+2tg(+1)
    #pragma unroll
    for (int mi = 0; mi < 2; mi++) {
        #pragma unroll
        for (int hi = 0; hi < 2; hi++) {
            int row = r0 + wm * 32 + mi * 16 + hi * 8 + g;
            if (row >= M) continue;
            #pragma unroll
            for (int nj = 0; nj < 8; nj++) {
                int col = wn * 64 + nj * 8 + 2 * tg;
                float v0 = acc[mi][nj][hi * 2 + 0];
                float v1 = acc[mi][nj][hi * 2 + 1];
                if (bias) {
                    float2 bi = *(const float2*)&bias[col];
                    v0 += bi.x; v1 += bi.y;
                }
                if (relu) { v0 = fmaxf(v0, 0.f); v1 = fmaxf(v1, 0.f); }
                float2 o; o.x = v0; o.y = v1;
                *(float2*)&Cout[(size_t)row * 128 + col] = o;
            }
        }
    }
    #undef LDG_TILE
    #undef STS_TILE
}

// ---------------- launch ----------------
extern "C" void kernel_launch(void* const* d_in, const int* in_sizes, int n_in,
                              void* d_out, int out_size) {
    const float* x      = (const float*)d_in[0];
    const void*  esrc   = d_in[1];
    const void*  edst   = d_in[2];
    const float* wcomp  = (const float*)d_in[3];
    const float* bases  = (const float*)d_in[4];   // [4,128,128] == flat [512,128]
    const float* loopw  = (const float*)d_in[5];
    const float* hbias  = (const float*)d_in[6];
    const float* ngnn   = (const float*)d_in[7];   // [2,128,128]
    float* out = (float*)d_out;

    __half *pYh, *pXh;
    float *pH1, *pH2;
    cudaGetSymbolAddress((void**)&pYh, g_Yh);
    cudaGetSymbolAddress((void**)&pXh, g_xh);
    cudaGetSymbolAddress((void**)&pH1, g_h1);
    cudaGetSymbolAddress((void**)&pH2, g_h2);

    k_detect<<<1, 32>>>(esrc, edst);
    k_zero<<<(RN + 255) / 256, 256>>>();
    k_x2h<<<(NN * DD / 4 + 255) / 256, 256>>>(x);
    k_degree<<<RE / 256, 256>>>(edst);
    k_scan1<<<SCAN_BLOCKS, 1024>>>();
    k_scan2<<<1, 1024>>>(SCAN_BLOCKS);
    k_scan3<<<(RN + 255) / 256, 256>>>();
    k_fill<<<RE / 256, 256>>>(esrc, edst);
    k_gather<<<(NN + 7) / 8, 256>>>(wcomp);

    int gblocks = (NN + 127) / 128;   // 782
    // h1 = relu(Yh @ bases_flat + xh @ loop_weight + bias)  [fused, fp16 A]
    k_gemm<<<gblocks, 256>>>(pYh, 512, bases, pXh, 128, loopw, NN, pH1, hbias, 1, 1);
    // h2 = relu(h1 @ ngnn_w[0])   [fp32 A]
    k_gemm<<<gblocks, 256>>>(pH1, 128, ngnn, nullptr, 0, nullptr, NN, pH2, nullptr, 1, 0);
    // out = relu(h2 @ ngnn_w[1])  [fp32 A]
    k_gemm<<<gblocks, 256>>>(pH2, 128, ngnn + 128 * 128, nullptr, 0, nullptr, NN, out, nullptr, 1, 0);
}